// round 4
// baseline (speedup 1.0000x reference)
#include <cuda_runtime.h>
#include <cuda_bf16.h>
#include <cstdint>

// SpatialAttentionLayer_23381801959766
//
// Reference math:
//   attn = softmax(fourier_maps(sensor_locs) @ W, axis=-1)   # rows sum to 1
//   out  = einsum('si,sjk->sjk', attn, X)                    # i summed out
//        = X * (row-sum of softmax) = X  (to fp32 ULP)
//
// Identity on X. Target: HBM streaming-copy roofline (2 x 142.6 MB).
// R2: float4 .cs MLP=4 -> 6.1 TB/s (77% DRAM, 37.8us kernel).
// R3: MLP=8 regressed occupancy (60.8%) -> neutral.
// R4: sm_103a 256-bit ld/st (ld.global.v8.f32 / st.global.v8.f32, LDG.E.256)
//     -- halves LSU dispatches and L1tex wavefront-queue entries at the same
//     bytes/thread as R2.

static constexpr int THREADS = 256;
// Each thread: 2 x 32B vector ops = 64 B. Per block: 256*64 = 16 KB.

__device__ __forceinline__ void ldg256(const float* __restrict__ p, float* v) {
    asm volatile(
        "ld.global.v8.f32 {%0,%1,%2,%3,%4,%5,%6,%7}, [%8];"
        : "=f"(v[0]), "=f"(v[1]), "=f"(v[2]), "=f"(v[3]),
          "=f"(v[4]), "=f"(v[5]), "=f"(v[6]), "=f"(v[7])
        : "l"(p));
}

__device__ __forceinline__ void stg256(float* __restrict__ p, const float* v) {
    asm volatile(
        "st.global.v8.f32 [%0], {%1,%2,%3,%4,%5,%6,%7,%8};"
        :: "l"(p),
           "f"(v[0]), "f"(v[1]), "f"(v[2]), "f"(v[3]),
           "f"(v[4]), "f"(v[5]), "f"(v[6]), "f"(v[7])
        : "memory");
}

__global__ __launch_bounds__(THREADS)
void stream_copy_kernel(const float* __restrict__ in, float* __restrict__ out) {
    // Thread t of block b handles floats [base, base+8) and
    // [base + THREADS*8, base + THREADS*8 + 8).
    size_t base = (size_t)blockIdx.x * (THREADS * 16) + (size_t)threadIdx.x * 8;

    float v0[8], v1[8];
    ldg256(in + base, v0);                       // front-batched loads
    ldg256(in + base + (size_t)THREADS * 8, v1);
    stg256(out + base, v0);
    stg256(out + base + (size_t)THREADS * 8, v1);
}

// Tail kernel for any remainder (not needed for this exact shape).
__global__ void stream_copy_tail(const float* __restrict__ in,
                                 float* __restrict__ out,
                                 size_t start, size_t n) {
    size_t i = start + blockIdx.x * (size_t)blockDim.x + threadIdx.x;
    if (i < n) out[i] = __ldcs(in + i);
}

extern "C" void kernel_launch(void* const* d_in, const int* in_sizes, int n_in,
                              void* d_out, int out_size) {
    const float* X = (const float*)d_in[0];
    float* out = (float*)d_out;

    size_t n = (size_t)out_size;                    // 35,651,584 floats
    size_t per_block = (size_t)THREADS * 16;        // 4096 floats/block
    size_t full_blocks = n / per_block;             // 8704 exact here

    if (full_blocks > 0) {
        stream_copy_kernel<<<(unsigned)full_blocks, THREADS>>>(X, out);
    }
    size_t done = full_blocks * per_block;
    if (done < n) {
        size_t rem = n - done;
        unsigned tb = (unsigned)((rem + 255) / 256);
        stream_copy_tail<<<tb, 256>>>(X, out, done, n);
    }
}